// round 14
// baseline (speedup 1.0000x reference)
#include <cuda_runtime.h>
#include <cuda_fp16.h>
#include <cstdint>

#define N_PTS   524288
#define M_NETS  64
#define HID     64
#define CAP     16384
#define GX      11               // persistent x-blocks per cell (704 CTAs ~ one wave @5/SM)
#define HIST_BLOCKS (N_PTS / 512)

// ---- device scratch ----
__device__ int   g_idx[M_NETS * CAP];   // per-cell regions: original point index
__device__ uint2 g_xh[M_NETS * CAP];    // per-cell regions: {f16x2(x,y), f16x2(z,1)}
__device__ int   g_cnt[M_NETS];         // zero at launch entry; reset by k_mma epilogue
__device__ int   g_done[M_NETS];        // CTA-arrival counters for the reset protocol

__device__ __forceinline__ int cell_of(float x0, float x1, float x2) {
    int i0 = (int)((x0 + 1.0f) * 2.0f);
    int i1 = (int)((x1 + 1.0f) * 2.0f);
    int i2 = (int)((x2 + 1.0f) * 2.0f);
    i0 = min(max(i0, 0), 3);
    i1 = min(max(i1, 0), 3);
    i2 = min(max(i2, 0), 3);
    return i2 + 4 * i1 + 16 * i0;
}

__device__ __forceinline__ uint32_t pack_f16x2(float v0, float v1) {
    uint32_t r;
    asm("cvt.rn.f16x2.f32 %0, %1, %2;" : "=r"(r) : "f"(v1), "f"(v0));  // {lo:v0, hi:v1}
    return r;
}

// Single-pass scatter: original index + packed fp16 X-fragment words.
__global__ void k_scatter(const float* __restrict__ x) {
    __shared__ int cnt[M_NETS];
    __shared__ int base[M_NETS];
    int t = threadIdx.x;
    if (t < M_NETS) cnt[t] = 0;
    __syncthreads();
    int i = blockIdx.x * 512 + t;
    float x0 = x[3 * i], x1 = x[3 * i + 1], x2 = x[3 * i + 2];
    int c = cell_of(x0, x1, x2);
    int r = atomicAdd(&cnt[c], 1);
    __syncthreads();
    if (t < M_NETS) {
        int n = cnt[t];
        base[t] = t * CAP + ((n > 0) ? atomicAdd(&g_cnt[t], n) : 0);
    }
    __syncthreads();
    int pos = base[c] + r;
    g_idx[pos] = i;
    g_xh[pos]  = make_uint2(pack_f16x2(x0, x1), pack_f16x2(x2, 1.0f));
}

__device__ __forceinline__ void mma_k16(float* d, const uint32_t* a, uint32_t b0, uint32_t b1) {
    asm volatile(
        "mma.sync.aligned.m16n8k16.row.col.f32.f16.f16.f32 "
        "{%0,%1,%2,%3}, {%4,%5,%6,%7}, {%8,%9}, {%0,%1,%2,%3};"
        : "+f"(d[0]), "+f"(d[1]), "+f"(d[2]), "+f"(d[3])
        : "r"(a[0]), "r"(a[1]), "r"(a[2]), "r"(a[3]), "r"(b0), "r"(b1));
}
// first-ks variant: C operand = {c0,c1,c0,c1} (row-independent bias b2)
__device__ __forceinline__ void mma_k16_c(float* d, const uint32_t* a, uint32_t b0, uint32_t b1,
                                          float c0, float c1) {
    asm volatile(
        "mma.sync.aligned.m16n8k16.row.col.f32.f16.f16.f32 "
        "{%0,%1,%2,%3}, {%4,%5,%6,%7}, {%8,%9}, {%10,%11,%10,%11};"
        : "=f"(d[0]), "=f"(d[1]), "=f"(d[2]), "=f"(d[3])
        : "r"(a[0]), "r"(a[1]), "r"(a[2]), "r"(a[3]), "r"(b0), "r"(b1),
          "f"(c0), "f"(c1));
}
// layer-1: m16n8k8, C = 0
__device__ __forceinline__ void mma_k8(float* d, uint32_t a0, uint32_t a1, uint32_t b) {
    asm volatile(
        "mma.sync.aligned.m16n8k8.row.col.f32.f16.f16.f32 "
        "{%0,%1,%2,%3}, {%4,%5}, {%6}, {%7,%7,%7,%7};"
        : "=f"(d[0]), "=f"(d[1]), "=f"(d[2]), "=f"(d[3])
        : "r"(a0), "r"(a1), "r"(b), "f"(0.0f));
}

// Persistent per-cell CTAs, mb-split for 5 CTAs/SM occupancy.
__global__ void __launch_bounds__(128, 5) k_mma(
    const float* __restrict__ W1, const float* __restrict__ b1,
    const float* __restrict__ W2, const float* __restrict__ b2,
    const float* __restrict__ W3, const float* __restrict__ b3,
    float* __restrict__ y)
{
    const int c      = blockIdx.y;
    const int cnt    = g_cnt[c];
    const int ntiles = (cnt + 127) >> 7;

    __shared__ __align__(8) uint32_t sB[2048];   // W2 frags, pair-interleaved
    __shared__ __align__(8) uint32_t sW1[256];   // W1aug k8 B-frags
    __shared__ __align__(8) float sb2[HID];
    __shared__ __align__(8) float sW3[HID];
    __shared__ float sb3s;

    const int t    = threadIdx.x;
    const int lane = t & 31;
    const int wid  = t >> 5;
    const int g    = lane >> 2;
    const int tg   = lane & 3;

    if ((int)blockIdx.x < ntiles) {
        // ---- staging: convert fragments directly from fp32 tensors ----
        const float* W2c = W2 + c * (HID * HID);
        for (int i = t; i < 2048; i += 128) {
            int w = i & 1, ln = (i >> 1) & 31, f = i >> 6;
            int ks = f >> 3, nb = f & 7;
            int k = ks * 16 + (ln & 3) * 2 + w * 8;
            int n = nb * 8 + (ln >> 2);
            sB[i] = pack_f16x2(__ldg(W2c + k * 64 + n), __ldg(W2c + (k + 1) * 64 + n));
        }
        for (int i = t; i < 256; i += 128) {
            int ln = i & 31, nb = i >> 5;
            int gg = ln >> 2, tt = ln & 3;
            int j = nb * 8 + gg;
            uint32_t v = 0;
            if (tt == 0) v = pack_f16x2(__ldg(W1 + c * 192 + j),
                                        __ldg(W1 + c * 192 + 64 + j));
            else if (tt == 1) v = pack_f16x2(__ldg(W1 + c * 192 + 128 + j),
                                             __ldg(b1 + c * 64 + j));
            sW1[i] = v;
        }
        if (t < HID) {
            sb2[t] = b2[c * 64 + t];
            sW3[t] = W3[c * 64 + t];
        }
        if (t == 0) sb3s = b3[c];
        __syncthreads();

        // per-thread W1 fragments (8 regs)
        uint32_t bW1[8];
        #pragma unroll
        for (int nb = 0; nb < 8; nb++) bW1[nb] = sW1[nb * 32 + lane];

        const uint2*  __restrict__ sBp  = (const uint2*)sB;
        const float2* __restrict__ sb2p = (const float2*)sb2;   // [nb*4+tg]
        const float2* __restrict__ sW3p = (const float2*)sW3;
        const uint32_t* __restrict__ xh32 = (const uint32_t*)g_xh;

        const int rbase = wid * 32 + g;

        for (int tile = blockIdx.x; tile < ntiles; tile += GX) {
            #pragma unroll
            for (int mb = 0; mb < 2; mb++) {
                const int row = tile * 128 + rbase + mb * 16;    // rows: row, row+8
                const int p   = c * CAP + row;

                uint32_t xw0 = (tg < 2 && row < cnt)     ? xh32[p * 2 + tg]       : 0u;
                uint32_t xw1 = (tg < 2 && row + 8 < cnt) ? xh32[(p + 8) * 2 + tg] : 0u;
                int oi0 = (tg == 0 && row < cnt)     ? g_idx[p]     : -1;
                int oi1 = (tg == 0 && row + 8 < cnt) ? g_idx[p + 8] : -1;

                float acc[8][4];

                #pragma unroll
                for (int ks = 0; ks < 4; ks++) {
                    // layer-1: A frags for this k16 chunk (= W1 nb pair 2ks,2ks+1)
                    uint32_t a2[4];
                    #pragma unroll
                    for (int half = 0; half < 2; half++) {
                        float d[4];
                        mma_k8(d, xw0, xw1, bW1[ks * 2 + half]);
                        a2[half * 2 + 0] = pack_f16x2(fmaxf(d[0], 0.f), fmaxf(d[1], 0.f));
                        a2[half * 2 + 1] = pack_f16x2(fmaxf(d[2], 0.f), fmaxf(d[3], 0.f));
                    }
                    // layer-2
                    #pragma unroll
                    for (int nb = 0; nb < 8; nb++) {
                        uint2 b = sBp[(ks * 8 + nb) * 32 + lane];
                        if (ks == 0) {
                            float2 cb = sb2p[nb * 4 + tg];
                            mma_k16_c(acc[nb], a2, b.x, b.y, cb.x, cb.y);
                        } else {
                            mma_k16(acc[nb], a2, b.x, b.y);
                        }
                    }
                }

                // epilogue: relu (b2 already in acc), dot W3, quad-reduce, store
                float s0 = 0.f, s1 = 0.f;
                #pragma unroll
                for (int nb = 0; nb < 8; nb++) {
                    float2 w3 = sW3p[nb * 4 + tg];
                    s0 = fmaf(fmaxf(acc[nb][0], 0.f), w3.x,
                         fmaf(fmaxf(acc[nb][1], 0.f), w3.y, s0));
                    s1 = fmaf(fmaxf(acc[nb][2], 0.f), w3.x,
                         fmaf(fmaxf(acc[nb][3], 0.f), w3.y, s1));
                }
                s0 += __shfl_xor_sync(0xFFFFFFFFu, s0, 1);
                s0 += __shfl_xor_sync(0xFFFFFFFFu, s0, 2);
                s1 += __shfl_xor_sync(0xFFFFFFFFu, s1, 1);
                s1 += __shfl_xor_sync(0xFFFFFFFFu, s1, 2);
                if (oi0 >= 0) y[oi0] = s0 + sb3s;
                if (oi1 >= 0) y[oi1] = s1 + sb3s;
            }
        }
        __syncthreads();
    }

    // ---- reset protocol: last of the GX CTAs for this cell zeroes g_cnt ----
    if (t == 0) {
        __threadfence();
        int v = atomicAdd(&g_done[c], 1);
        if (v == GX - 1) {
            g_cnt[c]  = 0;
            g_done[c] = 0;
        }
    }
}

extern "C" void kernel_launch(void* const* d_in, const int* in_sizes, int n_in,
                              void* d_out, int out_size) {
    const float* x  = (const float*)d_in[0];
    const float* W1 = (const float*)d_in[1];
    const float* b1 = (const float*)d_in[2];
    const float* W2 = (const float*)d_in[3];
    const float* b2 = (const float*)d_in[4];
    const float* W3 = (const float*)d_in[5];
    const float* b3 = (const float*)d_in[6];
    float* y = (float*)d_out;

    k_scatter<<<HIST_BLOCKS, 512>>>(x);
    dim3 grid(GX, M_NETS);
    k_mma<<<grid, 128>>>(W1, b1, W2, b2, W3, b3, y);
}

// round 15
// speedup vs baseline: 1.3298x; 1.3298x over previous
#include <cuda_runtime.h>
#include <cuda_fp16.h>
#include <cstdint>

#define N_PTS   524288
#define M_NETS  64
#define HID     64
#define CAP     16384
#define GX      9                // persistent x-blocks per cell (576 CTAs ~ one wave @4/SM)
#define HIST_BLOCKS (N_PTS / 512)

// ---- device scratch ----
__device__ int   g_idx[M_NETS * CAP];   // per-cell regions: original point index
__device__ uint2 g_xh[M_NETS * CAP];    // per-cell regions: {f16x2(x,y), f16x2(z,1)}
__device__ int   g_cnt[M_NETS];         // zero at launch entry; reset by k_mma epilogue
__device__ int   g_done[M_NETS];        // CTA-arrival counters for the reset protocol

__device__ __forceinline__ int cell_of(float x0, float x1, float x2) {
    int i0 = (int)((x0 + 1.0f) * 2.0f);
    int i1 = (int)((x1 + 1.0f) * 2.0f);
    int i2 = (int)((x2 + 1.0f) * 2.0f);
    i0 = min(max(i0, 0), 3);
    i1 = min(max(i1, 0), 3);
    i2 = min(max(i2, 0), 3);
    return i2 + 4 * i1 + 16 * i0;
}

__device__ __forceinline__ uint32_t pack_f16x2(float v0, float v1) {
    uint32_t r;
    asm("cvt.rn.f16x2.f32 %0, %1, %2;" : "=r"(r) : "f"(v1), "f"(v0));  // {lo:v0, hi:v1}
    return r;
}

// Single-pass scatter: original index + packed fp16 X-fragment words.
__global__ void k_scatter(const float* __restrict__ x) {
    __shared__ int cnt[M_NETS];
    __shared__ int base[M_NETS];
    int t = threadIdx.x;
    if (t < M_NETS) cnt[t] = 0;
    __syncthreads();
    int i = blockIdx.x * 512 + t;
    float x0 = x[3 * i], x1 = x[3 * i + 1], x2 = x[3 * i + 2];
    int c = cell_of(x0, x1, x2);
    int r = atomicAdd(&cnt[c], 1);
    __syncthreads();
    if (t < M_NETS) {
        int n = cnt[t];
        base[t] = t * CAP + ((n > 0) ? atomicAdd(&g_cnt[t], n) : 0);
    }
    __syncthreads();
    int pos = base[c] + r;
    g_idx[pos] = i;
    g_xh[pos]  = make_uint2(pack_f16x2(x0, x1), pack_f16x2(x2, 1.0f));
}

__device__ __forceinline__ void mma_k16(float* d, const uint32_t* a, uint32_t b0, uint32_t b1) {
    asm volatile(
        "mma.sync.aligned.m16n8k16.row.col.f32.f16.f16.f32 "
        "{%0,%1,%2,%3}, {%4,%5,%6,%7}, {%8,%9}, {%0,%1,%2,%3};"
        : "+f"(d[0]), "+f"(d[1]), "+f"(d[2]), "+f"(d[3])
        : "r"(a[0]), "r"(a[1]), "r"(a[2]), "r"(a[3]), "r"(b0), "r"(b1));
}
// first-ks variant: C operand = {c0,c1,c0,c1} (row-independent bias b2)
__device__ __forceinline__ void mma_k16_c(float* d, const uint32_t* a, uint32_t b0, uint32_t b1,
                                          float c0, float c1) {
    asm volatile(
        "mma.sync.aligned.m16n8k16.row.col.f32.f16.f16.f32 "
        "{%0,%1,%2,%3}, {%4,%5,%6,%7}, {%8,%9}, {%10,%11,%10,%11};"
        : "=f"(d[0]), "=f"(d[1]), "=f"(d[2]), "=f"(d[3])
        : "r"(a[0]), "r"(a[1]), "r"(a[2]), "r"(a[3]), "r"(b0), "r"(b1),
          "f"(c0), "f"(c1));
}
// layer-1: m16n8k8, C = 0
__device__ __forceinline__ void mma_k8(float* d, uint32_t a0, uint32_t a1, uint32_t b) {
    asm volatile(
        "mma.sync.aligned.m16n8k8.row.col.f32.f16.f16.f32 "
        "{%0,%1,%2,%3}, {%4,%5}, {%6}, {%7,%7,%7,%7};"
        : "=f"(d[0]), "=f"(d[1]), "=f"(d[2]), "=f"(d[3])
        : "r"(a0), "r"(a1), "r"(b), "f"(0.0f));
}

// Persistent per-cell CTAs. 64-point tiles; each warp owns one m16 block.
// All W2 B-fragments register-resident (loaded once) -> zero LDS in tile loop.
__global__ void __launch_bounds__(128, 4) k_mma(
    const float* __restrict__ W1, const float* __restrict__ b1,
    const float* __restrict__ W2, const float* __restrict__ b2,
    const float* __restrict__ W3, const float* __restrict__ b3,
    float* __restrict__ y)
{
    const int c      = blockIdx.y;
    const int cnt    = g_cnt[c];
    const int ntiles = (cnt + 63) >> 6;

    __shared__ __align__(8) uint32_t sB[2048];   // W2 frags, pair-interleaved
    __shared__ __align__(8) uint32_t sW1[256];   // W1aug k8 B-frags
    __shared__ __align__(8) float sb2[HID];
    __shared__ __align__(8) float sW3[HID];
    __shared__ float sb3s;

    const int t    = threadIdx.x;
    const int lane = t & 31;
    const int wid  = t >> 5;
    const int g    = lane >> 2;
    const int tg   = lane & 3;

    if ((int)blockIdx.x < ntiles) {
        // ---- staging: convert fragments directly from fp32 tensors ----
        const float* W2c = W2 + c * (HID * HID);
        for (int i = t; i < 2048; i += 128) {
            int w = i & 1, ln = (i >> 1) & 31, f = i >> 6;
            int ks = f >> 3, nb = f & 7;
            int k = ks * 16 + (ln & 3) * 2 + w * 8;
            int n = nb * 8 + (ln >> 2);
            sB[i] = pack_f16x2(__ldg(W2c + k * 64 + n), __ldg(W2c + (k + 1) * 64 + n));
        }
        for (int i = t; i < 256; i += 128) {
            int ln = i & 31, nb = i >> 5;
            int gg = ln >> 2, tt = ln & 3;
            int j = nb * 8 + gg;
            uint32_t v = 0;
            if (tt == 0) v = pack_f16x2(__ldg(W1 + c * 192 + j),
                                        __ldg(W1 + c * 192 + 64 + j));
            else if (tt == 1) v = pack_f16x2(__ldg(W1 + c * 192 + 128 + j),
                                             __ldg(b1 + c * 64 + j));
            sW1[i] = v;
        }
        if (t < HID) {
            sb2[t] = b2[c * 64 + t];
            sW3[t] = W3[c * 64 + t];
        }
        if (t == 0) sb3s = b3[c];
        __syncthreads();

        // ---- hoist all per-cell fragments into registers ----
        uint32_t bW1[8];
        #pragma unroll
        for (int nb = 0; nb < 8; nb++) bW1[nb] = sW1[nb * 32 + lane];

        const uint2* __restrict__ sBp = (const uint2*)sB;
        uint2 bB[4][8];                               // 64 regs, loaded ONCE
        #pragma unroll
        for (int ks = 0; ks < 4; ks++)
            #pragma unroll
            for (int nb = 0; nb < 8; nb++)
                bB[ks][nb] = sBp[(ks * 8 + nb) * 32 + lane];

        const float2* __restrict__ sb2p = (const float2*)sb2;   // [nb*4+tg]
        const float2* __restrict__ sW3p = (const float2*)sW3;
        const uint32_t* __restrict__ xh32 = (const uint32_t*)g_xh;

        const int rbase = wid * 16 + g;               // warp owns rows [wid*16, wid*16+16)

        for (int tile = blockIdx.x; tile < ntiles; tile += GX) {
            const int row = tile * 64 + rbase;        // rows: row, row+8
            const int p   = c * CAP + row;

            uint32_t xw0 = (tg < 2 && row < cnt)     ? xh32[p * 2 + tg]       : 0u;
            uint32_t xw1 = (tg < 2 && row + 8 < cnt) ? xh32[(p + 8) * 2 + tg] : 0u;
            int oi0 = (tg == 0 && row < cnt)     ? g_idx[p]     : -1;
            int oi1 = (tg == 0 && row + 8 < cnt) ? g_idx[p + 8] : -1;

            float acc[8][4];

            #pragma unroll
            for (int ks = 0; ks < 4; ks++) {
                // layer-1: A frags for this k16 chunk (= W1 nb pair 2ks,2ks+1)
                uint32_t a2[4];
                #pragma unroll
                for (int half = 0; half < 2; half++) {
                    float d[4];
                    mma_k8(d, xw0, xw1, bW1[ks * 2 + half]);
                    a2[half * 2 + 0] = pack_f16x2(fmaxf(d[0], 0.f), fmaxf(d[1], 0.f));
                    a2[half * 2 + 1] = pack_f16x2(fmaxf(d[2], 0.f), fmaxf(d[3], 0.f));
                }
                // layer-2: B operands already in registers
                #pragma unroll
                for (int nb = 0; nb < 8; nb++) {
                    uint2 b = bB[ks][nb];
                    if (ks == 0) {
                        float2 cb = sb2p[nb * 4 + tg];
                        mma_k16_c(acc[nb], a2, b.x, b.y, cb.x, cb.y);
                    } else {
                        mma_k16(acc[nb], a2, b.x, b.y);
                    }
                }
            }

            // epilogue: relu (b2 already in acc), dot W3, quad-reduce, store
            float s0 = 0.f, s1 = 0.f;
            #pragma unroll
            for (int nb = 0; nb < 8; nb++) {
                float2 w3 = sW3p[nb * 4 + tg];
                s0 = fmaf(fmaxf(acc[nb][0], 0.f), w3.x,
                     fmaf(fmaxf(acc[nb][1], 0.f), w3.y, s0));
                s1 = fmaf(fmaxf(acc[nb][2], 0.f), w3.x,
                     fmaf(fmaxf(acc[nb][3], 0.f), w3.y, s1));
            }
            s0 += __shfl_xor_sync(0xFFFFFFFFu, s0, 1);
            s0 += __shfl_xor_sync(0xFFFFFFFFu, s0, 2);
            s1 += __shfl_xor_sync(0xFFFFFFFFu, s1, 1);
            s1 += __shfl_xor_sync(0xFFFFFFFFu, s1, 2);
            if (oi0 >= 0) y[oi0] = s0 + sb3s;
            if (oi1 >= 0) y[oi1] = s1 + sb3s;
        }
        __syncthreads();
    }

    // ---- reset protocol: last of the GX CTAs for this cell zeroes g_cnt ----
    if (t == 0) {
        __threadfence();
        int v = atomicAdd(&g_done[c], 1);
        if (v == GX - 1) {
            g_cnt[c]  = 0;
            g_done[c] = 0;
        }
    }
}

extern "C" void kernel_launch(void* const* d_in, const int* in_sizes, int n_in,
                              void* d_out, int out_size) {
    const float* x  = (const float*)d_in[0];
    const float* W1 = (const float*)d_in[1];
    const float* b1 = (const float*)d_in[2];
    const float* W2 = (const float*)d_in[3];
    const float* b2 = (const float*)d_in[4];
    const float* W3 = (const float*)d_in[5];
    const float* b3 = (const float*)d_in[6];
    float* y = (float*)d_out;

    k_scatter<<<HIST_BLOCKS, 512>>>(x);
    dim3 grid(GX, M_NETS);
    k_mma<<<grid, 128>>>(W1, b1, W2, b2, W3, b3, y);
}